// round 4
// baseline (speedup 1.0000x reference)
#include <cuda_runtime.h>
#include <cuda_fp16.h>
#include <cstdint>

// ---------------- problem constants ----------------
#define BATCH    512
#define INDIM    4096
#define OUTDIM   11008
#define KC       32              // K elements per mainloop iter
#define ITERS    (INDIM / KC)    // 128
#define NTHREADS 256

// ---------------- smem layout (dynamic) ----------------
// X tile:    2 x (512 rows x 64B)        = 65536
// W decoded: 2 x ( 96 rows x 64B)        = 12288
// raw stored 2 x (96*32 int32 = 12288B)  = 24576
// raw sign   2 x 12288                   = 24576
// LUT        256 x 32 x 4B               = 32768
#define OFF_X    0
#define OFF_W    65536
#define OFF_RS   77824
#define OFF_RG   102400
#define OFF_LUT  126976
#define SMEM_TOTAL 159744

// fp16 copy of x, produced by a pre-pass (scratch via __device__ global)
__device__ __half g_x16[BATCH * INDIM];

// ---------------- PTX helpers (sm_80-class baseline only) ----------------
static __device__ __forceinline__ uint32_t smem_u32(const void* p) {
    uint32_t a;
    asm("{ .reg .u64 t; cvta.to.shared.u64 t, %1; cvt.u32.u64 %0, t; }"
        : "=r"(a) : "l"(p));
    return a;
}

#define CP_ASYNC_CG16(dst_smem, src_gen) do { \
    size_t _g = __cvta_generic_to_global((const void*)(src_gen)); \
    asm volatile("cp.async.cg.shared.global [%0], [%1], 16;" \
                 :: "r"((uint32_t)(dst_smem)), "l"(_g) : "memory"); \
} while (0)

#define CP_COMMIT() asm volatile("cp.async.commit_group;" ::: "memory")
#define CP_WAIT0()  asm volatile("cp.async.wait_group 0;" ::: "memory")

#define LDSM4(r0, r1, r2, r3, addr) \
    asm volatile("ldmatrix.sync.aligned.m8n8.x4.shared.b16 {%0,%1,%2,%3}, [%4];" \
                 : "=r"(r0), "=r"(r1), "=r"(r2), "=r"(r3) : "r"(addr))

#define MMA16816(d, a0, a1, a2, a3, b0, b1) \
    asm volatile("mma.sync.aligned.m16n8k16.row.col.f32.f16.f16.f32 " \
                 "{%0,%1,%2,%3},{%4,%5,%6,%7},{%8,%9},{%0,%1,%2,%3};" \
                 : "+f"((d)[0]), "+f"((d)[1]), "+f"((d)[2]), "+f"((d)[3]) \
                 : "r"(a0), "r"(a1), "r"(a2), "r"(a3), "r"(b0), "r"(b1))

// ---------------- kernel 1: x fp32 -> fp16 (once per launch) ----------------
__global__ void __launch_bounds__(256) convert_x_kernel(const float* __restrict__ x) {
    int i = blockIdx.x * 256 + threadIdx.x;          // 524288 threads * 4 floats
    float4 v = reinterpret_cast<const float4*>(x)[i];
    __half2* dst = reinterpret_cast<__half2*>(g_x16);
    dst[2 * i + 0] = __floats2half2_rn(v.x, v.y);
    dst[2 * i + 1] = __floats2half2_rn(v.z, v.w);
}

// ---------------- GEMM device helpers ----------------
// NP = number of 16-channel B groups per warp (2 -> N=64 CTA, 3 -> N=96 CTA)

template<int NP>
static __device__ __forceinline__ void load_tiles(
    uint32_t sb, int b, int k0,
    const int* __restrict__ stored, const int* __restrict__ sgn,
    int obase, int tid)
{
    // x tile: 512 rows x 32 fp16 (64B), swizzled chunk = c ^ ((row>>1)&3)
    const uint32_t bx = sb + OFF_X + (uint32_t)b * 32768u;
    #pragma unroll
    for (int i = 0; i < 8; ++i) {
        int cidx = i * 256 + tid;
        int row = cidx >> 2, c = cidx & 3;
        uint32_t dst = bx + (uint32_t)row * 64u
                     + (uint32_t)((c ^ ((row >> 1) & 3)) << 4);
        CP_ASYNC_CG16(dst, g_x16 + (size_t)row * INDIM + k0 + c * 8);
    }
    // raw W: NP*16*... = NP*256 chunks of 16B (4 int32) per array, linear layout
    const uint32_t rs = sb + OFF_RS + (uint32_t)b * 12288u;
    const uint32_t rg = sb + OFF_RG + (uint32_t)b * 12288u;
    #pragma unroll
    for (int i = 0; i < NP; ++i) {
        int cw = i * 256 + tid;
        int row = cw >> 3, q = cw & 7;
        size_t off = (size_t)(obase + row) * INDIM + (size_t)k0 + (size_t)q * 4;
        CP_ASYNC_CG16(rs + (uint32_t)cw * 16u, stored + off);
        CP_ASYNC_CG16(rg + (uint32_t)cw * 16u, sgn + off);
    }
}

template<int NP>
static __device__ __forceinline__ void decode_tile(uint32_t sb, int b, int tid, int lid)
{
    const uint32_t rs   = sb + OFF_RS + (uint32_t)b * 12288u;
    const uint32_t rg   = sb + OFF_RG + (uint32_t)b * 12288u;
    const uint32_t bw   = sb + OFF_W  + (uint32_t)b * 6144u;
    const uint32_t lutb = sb + OFF_LUT;
    #pragma unroll
    for (int i = 0; i < NP; ++i) {
        int cw = i * 256 + tid;
        uint32_t s0, s1, s2, s3, g0, g1, g2, g3;
        asm volatile("ld.shared.v4.b32 {%0,%1,%2,%3}, [%4];"
                     : "=r"(s0), "=r"(s1), "=r"(s2), "=r"(s3)
                     : "r"(rs + (uint32_t)cw * 16u));
        asm volatile("ld.shared.v4.b32 {%0,%1,%2,%3}, [%4];"
                     : "=r"(g0), "=r"(g1), "=r"(g2), "=r"(g3)
                     : "r"(rg + (uint32_t)cw * 16u));
        uint32_t h0, h1, h2, h3;
        uint32_t lane4 = (uint32_t)(lid << 2);
        asm volatile("ld.shared.b32 %0, [%1];" : "=r"(h0) : "r"(lutb + ((s0 << 7) | lane4)));
        asm volatile("ld.shared.b32 %0, [%1];" : "=r"(h1) : "r"(lutb + ((s1 << 7) | lane4)));
        asm volatile("ld.shared.b32 %0, [%1];" : "=r"(h2) : "r"(lutb + ((s2 << 7) | lane4)));
        asm volatile("ld.shared.b32 %0, [%1];" : "=r"(h3) : "r"(lutb + ((s3 << 7) | lane4)));
        h0 |= (g0 >> 16) & 0x8000u;        // sign=-1 -> 0xFFFFFFFF -> bit15
        h1 |= (g1 >> 16) & 0x8000u;
        h2 |= (g2 >> 16) & 0x8000u;
        h3 |= (g3 >> 16) & 0x8000u;
        uint32_t lo = h0 | (h1 << 16);
        uint32_t hi = h2 | (h3 << 16);
        int row = cw >> 3, q = cw & 7, c = q >> 1, hf = q & 1;
        uint32_t dst = bw + (uint32_t)row * 64u
                     + (uint32_t)((c ^ ((row >> 1) & 3)) << 4)
                     + (uint32_t)(hf << 3);
        asm volatile("st.shared.v2.b32 [%0], {%1,%2};"
                     :: "r"(dst), "r"(lo), "r"(hi) : "memory");
    }
}

template<int NP>
static __device__ __forceinline__ void compute_iter(
    uint32_t sb, int b, int warp_m, int warp_n, int lid,
    float (&acc)[8][2 * NP][4])
{
    const uint32_t bufX = sb + OFF_X + (uint32_t)b * 32768u;
    const uint32_t bufW = sb + OFF_W + (uint32_t)b * 6144u;
    const int lr = lid & 15, lc = lid >> 4;
    #pragma unroll
    for (int ks = 0; ks < 2; ++ks) {
        const int c = ks * 2 + lc;
        uint32_t br[2 * NP][2];
        #pragma unroll
        for (int p = 0; p < NP; ++p) {
            int row = warp_n * (NP * 16) + p * 16 + lr;
            uint32_t addr = bufW + (uint32_t)row * 64u
                          + (uint32_t)((c ^ ((row >> 1) & 3)) << 4);
            uint32_t r0, r1, r2, r3;
            LDSM4(r0, r1, r2, r3, addr);
            br[2 * p + 0][0] = r0; br[2 * p + 0][1] = r2;   // channels p*16..+7
            br[2 * p + 1][0] = r1; br[2 * p + 1][1] = r3;   // channels p*16+8..+15
        }
        #pragma unroll
        for (int mf = 0; mf < 8; ++mf) {
            int row = warp_m * 128 + mf * 16 + lr;
            uint32_t addr = bufX + (uint32_t)row * 64u
                          + (uint32_t)((c ^ ((row >> 1) & 3)) << 4);
            uint32_t a0, a1, a2, a3;
            LDSM4(a0, a1, a2, a3, addr);
            #pragma unroll
            for (int nf = 0; nf < 2 * NP; ++nf)
                MMA16816(acc[mf][nf], a0, a1, a2, a3, br[nf][0], br[nf][1]);
        }
    }
}

template<int NP>
static __device__ __forceinline__ void epilogue(
    const float (&acc)[8][2 * NP][4],
    float* __restrict__ out, const float* __restrict__ scale,
    const float* __restrict__ bias, int obase, int warp_m, int warp_n, int lid)
{
    const int g = lid >> 2, tig = lid & 3;
    #pragma unroll
    for (int nf = 0; nf < 2 * NP; ++nf) {
        int col = obase + warp_n * (NP * 16) + nf * 8 + tig * 2;
        float s0 = __ldg(scale + col), s1 = __ldg(scale + col + 1);
        float b0 = __ldg(bias + col),  b1 = __ldg(bias + col + 1);
        #pragma unroll
        for (int mf = 0; mf < 8; ++mf) {
            #pragma unroll
            for (int h = 0; h < 2; ++h) {
                int row = warp_m * 128 + mf * 16 + h * 8 + g;
                float2 v;
                v.x = (acc[mf][nf][2 * h + 0] + b0) * s0;
                v.y = (acc[mf][nf][2 * h + 1] + b1) * s1;
                *reinterpret_cast<float2*>(out + (size_t)row * OUTDIM + col) = v;
            }
        }
    }
}

template<int NP>
static __device__ __forceinline__ void run_gemm(
    uint32_t sb, const int* __restrict__ stored, const int* __restrict__ sgn,
    const float* __restrict__ scale, const float* __restrict__ bias,
    float* __restrict__ out, int obase)
{
    const int tid = threadIdx.x;
    const int lid = tid & 31, wid = tid >> 5;
    const int warp_m = wid >> 1, warp_n = wid & 1;

    float acc[8][2 * NP][4];
    #pragma unroll
    for (int i = 0; i < 8; ++i)
        #pragma unroll
        for (int j = 0; j < 2 * NP; ++j)
            #pragma unroll
            for (int k = 0; k < 4; ++k) acc[i][j][k] = 0.0f;

    load_tiles<NP>(sb, 0, 0, stored, sgn, obase, tid);
    CP_COMMIT();

    for (int it = 0; it < ITERS; ++it) {
        const int b = it & 1;
        CP_WAIT0();          // buffer b's loads complete (only 1 group pending)
        __syncthreads();     // visibility of cp.async data + prev-iter reads done
        decode_tile<NP>(sb, b, tid, lid);
        __syncthreads();     // decoded W visible; prev-iter ldmatrix reads retired
        if (it + 1 < ITERS) {
            load_tiles<NP>(sb, b ^ 1, (it + 1) * KC, stored, sgn, obase, tid);
            CP_COMMIT();
        }
        compute_iter<NP>(sb, b, warp_m, warp_n, lid, acc);
    }

    epilogue<NP>(acc, out, scale, bias, obase, warp_m, warp_n, lid);
}

// ---------------- kernel 2: fused decode + HMMA GEMM ----------------
__global__ void __launch_bounds__(NTHREADS, 1) qins_gemm_kernel(
    const int* __restrict__ stored, const int* __restrict__ sgn,
    const float* __restrict__ lminp, const float* __restrict__ lmaxp,
    const float* __restrict__ scale, const float* __restrict__ bias,
    float* __restrict__ out)
{
    extern __shared__ char smem[];
    const uint32_t sb = smem_u32(smem);
    const int tid = threadIdx.x;

    // Build 32x-replicated fp16 magnitude LUT (conflict-free: bank == lane)
    {
        float lmin = *lminp, lmax = *lmaxp;
        float w = expf(lmin + (255.0f - (float)tid) * (1.0f / 254.0f) * (lmax - lmin));
        uint32_t hb = (uint32_t)__half_as_ushort(__float2half_rn(w));
        uint32_t* lut = reinterpret_cast<uint32_t*>(smem + OFF_LUT);
        #pragma unroll
        for (int j = 0; j < 32; ++j) lut[tid * 32 + j] = hb;
    }
    // (first __syncthreads inside run_gemm's loop publishes the LUT)

    const int bid = blockIdx.x;
    if (bid < 100)
        run_gemm<2>(sb, stored, sgn, scale, bias, out, bid * 64);
    else
        run_gemm<3>(sb, stored, sgn, scale, bias, out, 6400 + (bid - 100) * 96);
}

// ---------------- launch ----------------
extern "C" void kernel_launch(void* const* d_in, const int* in_sizes, int n_in,
                              void* d_out, int out_size) {
    const float* x      = (const float*)d_in[0];
    const int*   stored = (const int*)d_in[1];
    const int*   sgn    = (const int*)d_in[2];
    const float* lmin   = (const float*)d_in[3];
    const float* lmax   = (const float*)d_in[4];
    const float* scale  = (const float*)d_in[5];
    const float* bias   = (const float*)d_in[6];
    float* out = (float*)d_out;

    cudaFuncSetAttribute(qins_gemm_kernel,
                         cudaFuncAttributeMaxDynamicSharedMemorySize, SMEM_TOTAL);

    // Pass 1: x fp32 -> fp16 scratch
    convert_x_kernel<<<(BATCH * INDIM) / (256 * 4), 256>>>(x);

    // Pass 2: one-wave fused decode + HMMA GEMM
    // 100 CTAs x 64 channels + 48 CTAs x 96 channels = 11008
    qins_gemm_kernel<<<148, NTHREADS, SMEM_TOTAL>>>(
        stored, sgn, lmin, lmax, scale, bias, out);
}

// round 5
// speedup vs baseline: 1.1845x; 1.1845x over previous
#include <cuda_runtime.h>
#include <cuda_fp16.h>
#include <cstdint>

// ---------------- problem constants ----------------
#define BATCH    512
#define INDIM    4096
#define OUTDIM   11008
#define KC       32              // K elements per mainloop iter
#define ITERS    (INDIM / KC)    // 128
#define NTHREADS 512

// ---------------- smem layout (dynamic, one CTA/SM) ----------------
// X tile:    2 x (512 rows x 64B)            = 65536
// W decoded: 2 x ( 96 rows x 64B, padded)    = 12288
// raw stored 2 x (80*32 int32 = 10240B)      = 20480
// raw sign   2 x 10240                       = 20480
// LUT        256 x 32 x 4B                   = 32768
#define OFF_X    0
#define OFF_W    65536
#define OFF_RS   77824
#define OFF_RG   98304
#define OFF_LUT  118784
#define SMEM_TOTAL 151552

#define XBUF_STRIDE 32768u
#define WBUF_STRIDE 6144u
#define RBUF_STRIDE 10240u

// fp16 copy of x, produced by a pre-pass (scratch via __device__ global)
__device__ __half g_x16[BATCH * INDIM];

// ---------------- PTX helpers (sm_80-class baseline only) ----------------
static __device__ __forceinline__ uint32_t smem_u32(const void* p) {
    uint32_t a;
    asm("{ .reg .u64 t; cvta.to.shared.u64 t, %1; cvt.u32.u64 %0, t; }"
        : "=r"(a) : "l"(p));
    return a;
}

#define CP_ASYNC_CG16(dst_smem, src_gen) do { \
    size_t _g = __cvta_generic_to_global((const void*)(src_gen)); \
    asm volatile("cp.async.cg.shared.global [%0], [%1], 16;" \
                 :: "r"((uint32_t)(dst_smem)), "l"(_g) : "memory"); \
} while (0)

#define CP_COMMIT() asm volatile("cp.async.commit_group;" ::: "memory")
#define CP_WAIT0()  asm volatile("cp.async.wait_group 0;" ::: "memory")

#define LDSM4(r0, r1, r2, r3, addr) \
    asm volatile("ldmatrix.sync.aligned.m8n8.x4.shared.b16 {%0,%1,%2,%3}, [%4];" \
                 : "=r"(r0), "=r"(r1), "=r"(r2), "=r"(r3) : "r"(addr))

#define MMA16816(d, a0, a1, a2, a3, b0, b1) \
    asm volatile("mma.sync.aligned.m16n8k16.row.col.f32.f16.f16.f32 " \
                 "{%0,%1,%2,%3},{%4,%5,%6,%7},{%8,%9},{%0,%1,%2,%3};" \
                 : "+f"((d)[0]), "+f"((d)[1]), "+f"((d)[2]), "+f"((d)[3]) \
                 : "r"(a0), "r"(a1), "r"(a2), "r"(a3), "r"(b0), "r"(b1))

// 16B-chunk swizzle within a 64B row: c ^ ((row>>1)&3)
static __device__ __forceinline__ uint32_t swz(int c, int row) {
    return (uint32_t)((c ^ ((row >> 1) & 3)) << 4);
}

// ---------------- kernel 1: x fp32 -> fp16 (once per launch) ----------------
__global__ void __launch_bounds__(256) convert_x_kernel(const float* __restrict__ x) {
    int i = blockIdx.x * 256 + threadIdx.x;          // 524288 threads * 4 floats
    float4 v = reinterpret_cast<const float4*>(x)[i];
    __half2* dst = reinterpret_cast<__half2*>(g_x16);
    dst[2 * i + 0] = __floats2half2_rn(v.x, v.y);
    dst[2 * i + 1] = __floats2half2_rn(v.z, v.w);
}

// ---------------- GEMM device helpers ----------------
// NC = channels per CTA (64 or 80). Warp tile: 64 batch x NC/2 channels.

template<int NC>
static __device__ __forceinline__ void load_tiles(
    uint32_t sb, int b, int k0,
    const int* __restrict__ stored, const int* __restrict__ sgn,
    int obase, int tid)
{
    // X tile: 512 rows x 32 fp16 (64B rows), 2048 16B chunks, 4 per thread
    const uint32_t bx = sb + OFF_X + (uint32_t)b * XBUF_STRIDE;
    #pragma unroll
    for (int i = 0; i < 4; ++i) {
        int cidx = i * NTHREADS + tid;
        int row = cidx >> 2, c = cidx & 3;
        uint32_t dst = bx + (uint32_t)row * 64u + swz(c, row);
        CP_ASYNC_CG16(dst, g_x16 + (size_t)row * INDIM + k0 + c * 8);
    }
    // Raw W: NC rows x 32 int32 per array -> NC*8 16B chunks
    const uint32_t rs = sb + OFF_RS + (uint32_t)b * RBUF_STRIDE;
    const uint32_t rg = sb + OFF_RG + (uint32_t)b * RBUF_STRIDE;
    #pragma unroll
    for (int cw = tid; cw < NC * 8; cw += NTHREADS) {
        int row = cw >> 3, q = cw & 7;
        size_t off = (size_t)(obase + row) * INDIM + (size_t)k0 + (size_t)q * 4;
        CP_ASYNC_CG16(rs + (uint32_t)cw * 16u, stored + off);
        CP_ASYNC_CG16(rg + (uint32_t)cw * 16u, sgn + off);
    }
}

template<int NC>
static __device__ __forceinline__ void decode_tile(uint32_t sb, int b, int tid, int lid)
{
    const uint32_t rs   = sb + OFF_RS + (uint32_t)b * RBUF_STRIDE;
    const uint32_t rg   = sb + OFF_RG + (uint32_t)b * RBUF_STRIDE;
    const uint32_t bw   = sb + OFF_W  + (uint32_t)b * WBUF_STRIDE;
    const uint32_t lutb = sb + OFF_LUT + (uint32_t)(lid << 2);
    #pragma unroll
    for (int cw = tid; cw < NC * 8; cw += NTHREADS) {
        uint32_t s0, s1, s2, s3, g0, g1, g2, g3;
        asm volatile("ld.shared.v4.b32 {%0,%1,%2,%3}, [%4];"
                     : "=r"(s0), "=r"(s1), "=r"(s2), "=r"(s3)
                     : "r"(rs + (uint32_t)cw * 16u));
        asm volatile("ld.shared.v4.b32 {%0,%1,%2,%3}, [%4];"
                     : "=r"(g0), "=r"(g1), "=r"(g2), "=r"(g3)
                     : "r"(rg + (uint32_t)cw * 16u));
        uint32_t h0, h1, h2, h3;
        asm volatile("ld.shared.b32 %0, [%1];" : "=r"(h0) : "r"(lutb + (s0 << 7)));
        asm volatile("ld.shared.b32 %0, [%1];" : "=r"(h1) : "r"(lutb + (s1 << 7)));
        asm volatile("ld.shared.b32 %0, [%1];" : "=r"(h2) : "r"(lutb + (s2 << 7)));
        asm volatile("ld.shared.b32 %0, [%1];" : "=r"(h3) : "r"(lutb + (s3 << 7)));
        h0 |= (g0 >> 16) & 0x8000u;        // sign=-1 -> 0xFFFF.... -> bit15
        h1 |= (g1 >> 16) & 0x8000u;
        h2 |= (g2 >> 16) & 0x8000u;
        h3 |= (g3 >> 16) & 0x8000u;
        uint32_t lo = h0 | (h1 << 16);
        uint32_t hi = h2 | (h3 << 16);
        int row = cw >> 3, q = cw & 7, c = q >> 1, hf = q & 1;
        uint32_t dst = bw + (uint32_t)row * 64u + swz(c, row) + (uint32_t)(hf << 3);
        asm volatile("st.shared.v2.b32 [%0], {%1,%2};"
                     :: "r"(dst), "r"(lo), "r"(hi) : "memory");
    }
}

template<int NC>
static __device__ __forceinline__ void compute_iter(
    uint32_t sb, int b, int warp_m, int warp_n, int lid,
    float (&acc)[4][NC / 16][4])
{
    constexpr int WARP_CH = NC / 2;            // 32 or 40
    constexpr int NFRAG   = WARP_CH / 8;       // 4 or 5
    constexpr int NSTEP   = (WARP_CH + 15) / 16; // 2 or 3 (last over-reads pad)
    const uint32_t bufX = sb + OFF_X + (uint32_t)b * XBUF_STRIDE;
    const uint32_t bufW = sb + OFF_W + (uint32_t)b * WBUF_STRIDE;
    const int lr = lid & 15, lc = lid >> 4;
    #pragma unroll
    for (int ks = 0; ks < 2; ++ks) {
        const int c = ks * 2 + lc;
        uint32_t br[NFRAG][2];
        #pragma unroll
        for (int p = 0; p < NSTEP; ++p) {
            int row = warp_n * WARP_CH + p * 16 + lr;   // may read into pad rows
            uint32_t addr = bufW + (uint32_t)row * 64u + swz(c, row);
            uint32_t r0, r1, r2, r3;
            LDSM4(r0, r1, r2, r3, addr);
            br[2 * p + 0][0] = r0; br[2 * p + 0][1] = r2;
            if (2 * p + 1 < NFRAG) { br[2 * p + 1][0] = r1; br[2 * p + 1][1] = r3; }
        }
        #pragma unroll
        for (int mf = 0; mf < 4; ++mf) {
            int row = warp_m * 64 + mf * 16 + lr;
            uint32_t addr = bufX + (uint32_t)row * 64u + swz(c, row);
            uint32_t a0, a1, a2, a3;
            LDSM4(a0, a1, a2, a3, addr);
            #pragma unroll
            for (int nf = 0; nf < NFRAG; ++nf)
                MMA16816(acc[mf][nf], a0, a1, a2, a3, br[nf][0], br[nf][1]);
        }
    }
}

template<int NC>
static __device__ __forceinline__ void epilogue(
    const float (&acc)[4][NC / 16][4],
    float* __restrict__ out, const float* __restrict__ scale,
    const float* __restrict__ bias, int obase, int warp_m, int warp_n, int lid)
{
    constexpr int WARP_CH = NC / 2;
    constexpr int NFRAG   = WARP_CH / 8;
    const int g = lid >> 2, tig = lid & 3;
    #pragma unroll
    for (int nf = 0; nf < NFRAG; ++nf) {
        int col = obase + warp_n * WARP_CH + nf * 8 + tig * 2;
        float s0 = __ldg(scale + col), s1 = __ldg(scale + col + 1);
        float b0 = __ldg(bias + col),  b1 = __ldg(bias + col + 1);
        #pragma unroll
        for (int mf = 0; mf < 4; ++mf) {
            #pragma unroll
            for (int h = 0; h < 2; ++h) {
                int row = warp_m * 64 + mf * 16 + h * 8 + g;
                float2 v;
                v.x = (acc[mf][nf][2 * h + 0] + b0) * s0;
                v.y = (acc[mf][nf][2 * h + 1] + b1) * s1;
                *reinterpret_cast<float2*>(out + (size_t)row * OUTDIM + col) = v;
            }
        }
    }
}

template<int NC>
static __device__ __forceinline__ void run_gemm(
    uint32_t sb, const int* __restrict__ stored, const int* __restrict__ sgn,
    const float* __restrict__ scale, const float* __restrict__ bias,
    float* __restrict__ out, int obase)
{
    const int tid = threadIdx.x;
    const int lid = tid & 31, wid = tid >> 5;
    const int warp_m = wid >> 1, warp_n = wid & 1;   // 8 x 2 warp grid

    float acc[4][NC / 16][4];
    #pragma unroll
    for (int i = 0; i < 4; ++i)
        #pragma unroll
        for (int j = 0; j < NC / 16; ++j)
            #pragma unroll
            for (int k = 0; k < 4; ++k) acc[i][j][k] = 0.0f;

    load_tiles<NC>(sb, 0, 0, stored, sgn, obase, tid);
    CP_COMMIT();

    for (int it = 0; it < ITERS; ++it) {
        const int b = it & 1;
        CP_WAIT0();          // buffer b's cp.async complete
        __syncthreads();     // data visible to all (also publishes LUT at it=0)
        decode_tile<NC>(sb, b, tid, lid);
        __syncthreads();     // decoded W visible; all threads past compute(it-1)
        if (it + 1 < ITERS) {
            load_tiles<NC>(sb, b ^ 1, (it + 1) * KC, stored, sgn, obase, tid);
            CP_COMMIT();
        }
        compute_iter<NC>(sb, b, warp_m, warp_n, lid, acc);
    }

    epilogue<NC>(acc, out, scale, bias, obase, warp_m, warp_n, lid);
}

// ---------------- kernel 2: fused decode + HMMA GEMM ----------------
__global__ void __launch_bounds__(NTHREADS, 1) qins_gemm_kernel(
    const int* __restrict__ stored, const int* __restrict__ sgn,
    const float* __restrict__ lminp, const float* __restrict__ lmaxp,
    const float* __restrict__ scale, const float* __restrict__ bias,
    float* __restrict__ out)
{
    extern __shared__ char smem[];
    const uint32_t sb = smem_u32(smem);
    const int tid = threadIdx.x;

    // Build 32x-replicated fp16 magnitude LUT (bank == lane: conflict-free)
    if (tid < 256) {
        float lmin = *lminp, lmax = *lmaxp;
        float w = expf(lmin + (255.0f - (float)tid) * (1.0f / 254.0f) * (lmax - lmin));
        uint32_t hb = (uint32_t)__half_as_ushort(__float2half_rn(w));
        uint32_t* lut = reinterpret_cast<uint32_t*>(smem + OFF_LUT);
        #pragma unroll
        for (int j = 0; j < 32; ++j) lut[tid * 32 + j] = hb;
    }
    // (first __syncthreads inside run_gemm publishes the LUT)

    const int bid = blockIdx.x;
    if (bid < 52)
        run_gemm<64>(sb, stored, sgn, scale, bias, out, bid * 64);
    else
        run_gemm<80>(sb, stored, sgn, scale, bias, out, 3328 + (bid - 52) * 80);
}

// ---------------- launch ----------------
extern "C" void kernel_launch(void* const* d_in, const int* in_sizes, int n_in,
                              void* d_out, int out_size) {
    const float* x      = (const float*)d_in[0];
    const int*   stored = (const int*)d_in[1];
    const int*   sgn    = (const int*)d_in[2];
    const float* lmin   = (const float*)d_in[3];
    const float* lmax   = (const float*)d_in[4];
    const float* scale  = (const float*)d_in[5];
    const float* bias   = (const float*)d_in[6];
    float* out = (float*)d_out;

    cudaFuncSetAttribute(qins_gemm_kernel,
                         cudaFuncAttributeMaxDynamicSharedMemorySize, SMEM_TOTAL);

    // Pass 1: x fp32 -> fp16 scratch
    convert_x_kernel<<<(BATCH * INDIM) / (256 * 4), 256>>>(x);

    // Pass 2: one exact wave — 52 CTAs x 64ch + 96 CTAs x 80ch = 11008
    qins_gemm_kernel<<<148, NTHREADS, SMEM_TOTAL>>>(
        stored, sgn, lmin, lmax, scale, bias, out);
}

// round 9
// speedup vs baseline: 1.2666x; 1.0693x over previous
#include <cuda_runtime.h>
#include <cuda_fp16.h>
#include <cstdint>

// ---------------- problem constants ----------------
#define BATCH    512
#define INDIM    4096
#define OUTDIM   11008
#define KC       32              // K elements per mainloop iter
#define ITERS    (INDIM / KC)    // 128
#define NTHREADS 512

// ---------------- smem layout (dynamic, one CTA/SM) ----------------
// X tile:    3 x (512 rows x 64B) = 98304
// W decoded: 3 x ( 96 rows x 64B) = 18432
// raw:       2 x (80*32*(4+4)B)   = 40960
#define OFF_X    0
#define OFF_W    98304
#define OFF_RS   116736
#define SMEM_TOTAL 198656

#define XBUF_STRIDE 32768u
#define WBUF_STRIDE 6144u
#define RBUF_STRIDE 10240u
#define RS_BUF(i) (OFF_RS + (uint32_t)(i) * RBUF_STRIDE)          // 116736 / 126976
#define RG_BUF(i) (OFF_RS + 20480u + (uint32_t)(i) * RBUF_STRIDE) // 137216 / 147456

// fp16 copy of x, produced by a pre-pass (scratch via __device__ global)
__device__ __half g_x16[BATCH * INDIM];

// ---------------- PTX helpers (sm_80-class baseline only) ----------------
static __device__ __forceinline__ uint32_t smem_u32(const void* p) {
    uint32_t a;
    asm("{ .reg .u64 t; cvta.to.shared.u64 t, %1; cvt.u32.u64 %0, t; }"
        : "=r"(a) : "l"(p));
    return a;
}

#define CP_ASYNC_CG16(dst_smem, src_gen) do { \
    size_t _g = __cvta_generic_to_global((const void*)(src_gen)); \
    asm volatile("cp.async.cg.shared.global [%0], [%1], 16;" \
                 :: "r"((uint32_t)(dst_smem)), "l"(_g) : "memory"); \
} while (0)

#define CP_COMMIT() asm volatile("cp.async.commit_group;" ::: "memory")
#define CP_WAIT(n)  asm volatile("cp.async.wait_group %0;" :: "n"(n) : "memory")

#define LDSM4(r0, r1, r2, r3, addr) \
    asm volatile("ldmatrix.sync.aligned.m8n8.x4.shared.b16 {%0,%1,%2,%3}, [%4];" \
                 : "=r"(r0), "=r"(r1), "=r"(r2), "=r"(r3) : "r"(addr))

#define MMA16816(d, a0, a1, a2, a3, b0, b1) \
    asm volatile("mma.sync.aligned.m16n8k16.row.col.f32.f16.f16.f32 " \
                 "{%0,%1,%2,%3},{%4,%5,%6,%7},{%8,%9},{%0,%1,%2,%3};" \
                 : "+f"((d)[0]), "+f"((d)[1]), "+f"((d)[2]), "+f"((d)[3]) \
                 : "r"(a0), "r"(a1), "r"(a2), "r"(a3), "r"(b0), "r"(b1))

// pack two fp32 into fp16x2 (lo = a, hi = b)
static __device__ __forceinline__ uint32_t pack_f16x2(float a, float b) {
    uint32_t r;
    asm("cvt.rn.f16x2.f32 %0, %1, %2;" : "=r"(r) : "f"(b), "f"(a));
    return r;
}

// 16B-chunk swizzle within a 64B row: c ^ ((row>>1)&3)
static __device__ __forceinline__ uint32_t swz(int c, int row) {
    return (uint32_t)((c ^ ((row >> 1) & 3)) << 4);
}

static __device__ __forceinline__ float ex2f(float x) {
    float r;
    asm("ex2.approx.f32 %0, %1;" : "=f"(r) : "f"(x));
    return r;
}

// ---------------- kernel 1: x fp32 -> fp16 (once per launch) ----------------
__global__ void __launch_bounds__(256) convert_x_kernel(const float* __restrict__ x) {
    int i = blockIdx.x * 256 + threadIdx.x;          // 524288 threads * 4 floats
    float4 v = reinterpret_cast<const float4*>(x)[i];
    uint2* dst = reinterpret_cast<uint2*>(g_x16);
    uint2 o;
    o.x = pack_f16x2(v.x, v.y);
    o.y = pack_f16x2(v.z, v.w);
    dst[i] = o;
}

// ---------------- GEMM device helpers ----------------
// NC = channels per CTA (64 or 80). Warp tile: 64 batch x NC/2 channels.

static __device__ __forceinline__ void load_x(uint32_t xbase, int k0, int tid)
{
    #pragma unroll
    for (int i = 0; i < 4; ++i) {
        int cidx = i * NTHREADS + tid;
        int row = cidx >> 2, c = cidx & 3;
        uint32_t dst = xbase + (uint32_t)row * 64u + swz(c, row);
        CP_ASYNC_CG16(dst, g_x16 + (size_t)row * INDIM + k0 + c * 8);
    }
}

// Each thread owns chunks cw = tid, tid+512, ... (identical mapping in decode!)
template<int NC>
static __device__ __forceinline__ void load_raw(
    uint32_t rs, uint32_t rg,
    const int* __restrict__ stored, const int* __restrict__ sgn,
    int obase, int k0, int tid)
{
    #pragma unroll
    for (int cw = tid; cw < NC * 8; cw += NTHREADS) {
        int row = cw >> 3, q = cw & 7;
        size_t off = (size_t)(obase + row) * INDIM + (size_t)k0 + (size_t)q * 4;
        CP_ASYNC_CG16(rs + (uint32_t)cw * 16u, stored + off);
        CP_ASYNC_CG16(rg + (uint32_t)cw * 16u, sgn + off);
    }
}

template<int NC>
static __device__ __forceinline__ void decode_tile(
    uint32_t rs, uint32_t rg, uint32_t wdst, int tid, float Ac, float Bc)
{
    #pragma unroll
    for (int cw = tid; cw < NC * 8; cw += NTHREADS) {
        uint32_t s0, s1, s2, s3, g0, g1, g2, g3;
        asm volatile("ld.shared.v4.b32 {%0,%1,%2,%3}, [%4];"
                     : "=r"(s0), "=r"(s1), "=r"(s2), "=r"(s3)
                     : "r"(rs + (uint32_t)cw * 16u));
        asm volatile("ld.shared.v4.b32 {%0,%1,%2,%3}, [%4];"
                     : "=r"(g0), "=r"(g1), "=r"(g2), "=r"(g3)
                     : "r"(rg + (uint32_t)cw * 16u));
        float w0 = ex2f(fmaf((float)(int)s0, Bc, Ac));
        float w1 = ex2f(fmaf((float)(int)s1, Bc, Ac));
        float w2 = ex2f(fmaf((float)(int)s2, Bc, Ac));
        float w3 = ex2f(fmaf((float)(int)s3, Bc, Ac));
        uint32_t lo = pack_f16x2(w0, w1);
        uint32_t hi = pack_f16x2(w2, w3);
        // sign = -1 -> int32 0xFFFFFFFF -> set fp16 sign bit
        lo |= ((g0 >> 16) & 0x8000u) | (g1 & 0x80000000u);
        hi |= ((g2 >> 16) & 0x8000u) | (g3 & 0x80000000u);
        int row = cw >> 3, q = cw & 7, c = q >> 1, hf = q & 1;
        uint32_t dst = wdst + (uint32_t)row * 64u + swz(c, row) + (uint32_t)(hf << 3);
        asm volatile("st.shared.v2.b32 [%0], {%1,%2};"
                     :: "r"(dst), "r"(lo), "r"(hi) : "memory");
    }
}

template<int NC>
static __device__ __forceinline__ void compute_iter(
    uint32_t bufX, uint32_t bufW, int warp_m, int warp_n, int lid,
    float (&acc)[4][NC / 16][4])
{
    constexpr int WARP_CH = NC / 2;              // 32 or 40
    constexpr int NFRAG   = WARP_CH / 8;         // 4 or 5
    constexpr int NSTEP   = (WARP_CH + 15) / 16; // 2 or 3 (last over-reads pad)
    const int lr = lid & 15, lc = lid >> 4;
    #pragma unroll
    for (int ks = 0; ks < 2; ++ks) {
        const int c = ks * 2 + lc;
        uint32_t br[NFRAG][2];
        #pragma unroll
        for (int p = 0; p < NSTEP; ++p) {
            int row = warp_n * WARP_CH + p * 16 + lr;
            uint32_t addr = bufW + (uint32_t)row * 64u + swz(c, row);
            uint32_t r0, r1, r2, r3;
            LDSM4(r0, r1, r2, r3, addr);
            br[2 * p + 0][0] = r0; br[2 * p + 0][1] = r2;
            if (2 * p + 1 < NFRAG) { br[2 * p + 1][0] = r1; br[2 * p + 1][1] = r3; }
        }
        #pragma unroll
        for (int mf = 0; mf < 4; ++mf) {
            int row = warp_m * 64 + mf * 16 + lr;
            uint32_t addr = bufX + (uint32_t)row * 64u + swz(c, row);
            uint32_t a0, a1, a2, a3;
            LDSM4(a0, a1, a2, a3, addr);
            #pragma unroll
            for (int nf = 0; nf < NFRAG; ++nf)
                MMA16816(acc[mf][nf], a0, a1, a2, a3, br[nf][0], br[nf][1]);
        }
    }
}

template<int NC>
static __device__ __forceinline__ void epilogue(
    const float (&acc)[4][NC / 16][4],
    float* __restrict__ out, const float* __restrict__ scale,
    const float* __restrict__ bias, int obase, int warp_m, int warp_n, int lid)
{
    constexpr int WARP_CH = NC / 2;
    constexpr int NFRAG   = WARP_CH / 8;
    const int g = lid >> 2, tig = lid & 3;
    #pragma unroll
    for (int nf = 0; nf < NFRAG; ++nf) {
        int col = obase + warp_n * WARP_CH + nf * 8 + tig * 2;
        float s0 = __ldg(scale + col), s1 = __ldg(scale + col + 1);
        float b0 = __ldg(bias + col),  b1 = __ldg(bias + col + 1);
        #pragma unroll
        for (int mf = 0; mf < 4; ++mf) {
            #pragma unroll
            for (int h = 0; h < 2; ++h) {
                int row = warp_m * 64 + mf * 16 + h * 8 + g;
                float2 v;
                v.x = (acc[mf][nf][2 * h + 0] + b0) * s0;
                v.y = (acc[mf][nf][2 * h + 1] + b1) * s1;
                *reinterpret_cast<float2*>(out + (size_t)row * OUTDIM + col) = v;
            }
        }
    }
}

template<int NC>
static __device__ __forceinline__ void run_gemm(
    uint32_t sb, const int* __restrict__ stored, const int* __restrict__ sgn,
    const float* __restrict__ scale, const float* __restrict__ bias,
    float* __restrict__ out, int obase, float Ac, float Bc)
{
    const int tid = threadIdx.x;
    const int lid = tid & 31, wid = tid >> 5;
    const int warp_m = wid >> 1, warp_n = wid & 1;   // 8 x 2 warp grid

    float acc[4][NC / 16][4];
    #pragma unroll
    for (int i = 0; i < 4; ++i)
        #pragma unroll
        for (int j = 0; j < NC / 16; ++j)
            #pragma unroll
            for (int k = 0; k < 4; ++k) acc[i][j][k] = 0.0f;

    // ---------------- prologue ----------------
    // G0 = {X(0), raw(0)}, G1 = {X(1), raw(1)}
    load_x(sb + OFF_X, 0, tid);
    load_raw<NC>(sb + RS_BUF(0), sb + RG_BUF(0), stored, sgn, obase, 0, tid);
    CP_COMMIT();
    load_x(sb + OFF_X + XBUF_STRIDE, KC, tid);
    load_raw<NC>(sb + RS_BUF(1), sb + RG_BUF(1), stored, sgn, obase, KC, tid);
    CP_COMMIT();
    CP_WAIT(1);   // G0 done (own chunks)
    decode_tile<NC>(sb + RS_BUF(0), sb + RG_BUF(0), sb + OFF_W, tid, Ac, Bc);
    // G2 = {raw(2)} -> raw[0] (own chunks just decoded by this thread)
    load_raw<NC>(sb + RS_BUF(0), sb + RG_BUF(0), stored, sgn, obase, 2 * KC, tid);
    CP_COMMIT();
    CP_WAIT(1);   // G1 done
    decode_tile<NC>(sb + RS_BUF(1), sb + RG_BUF(1), sb + OFF_W + WBUF_STRIDE, tid, Ac, Bc);
    CP_WAIT(0);   // G2 done (raw(2) ready for region 0's decode)
    __syncthreads();   // X(0), X(1), Wdec(0), Wdec(1) visible to all

    // ---------------- main loop: ONE sync per region ----------------
    uint32_t xc = sb + OFF_X;
    uint32_t x1 = sb + OFF_X + XBUF_STRIDE;
    uint32_t x2 = sb + OFF_X + 2 * XBUF_STRIDE;
    uint32_t w0 = sb + OFF_W;
    uint32_t w1 = sb + OFF_W + WBUF_STRIDE;
    uint32_t w2 = sb + OFF_W + 2 * WBUF_STRIDE;

    for (int it = 0; it < ITERS; ++it) {
        // decode(it+2): raw(it+2) lives in raw[it&1]; target Wdec two ahead
        if (it + 2 < ITERS)
            decode_tile<NC>(sb + RS_BUF(it & 1), sb + RG_BUF(it & 1), w2, tid, Ac, Bc);
        // issue raw(it+3) -> raw[(it+3)&1] (own chunks decoded at region it-1)
        if (it + 3 < ITERS)
            load_raw<NC>(sb + RS_BUF((it + 3) & 1), sb + RG_BUF((it + 3) & 1),
                         stored, sgn, obase, (it + 3) * KC, tid);
        // issue X(it+2) -> x2 (held X(it-1), readers fenced by last sync)
        if (it + 2 < ITERS)
            load_x(x2, (it + 2) * KC, tid);
        CP_COMMIT();

        compute_iter<NC>(xc, w0, warp_m, warp_n, lid, acc);

        CP_WAIT(0);        // own chunks of everything issued so far
        __syncthreads();   // cross-thread visibility + buffer recycling fence

        uint32_t t;
        t = xc; xc = x1; x1 = x2; x2 = t;
        t = w0; w0 = w1; w1 = w2; w2 = t;
    }

    epilogue<NC>(acc, out, scale, bias, obase, warp_m, warp_n, lid);
}

// ---------------- kernel 2: fused decode + HMMA GEMM ----------------
__global__ void __launch_bounds__(NTHREADS, 1) qins_gemm_kernel(
    const int* __restrict__ stored, const int* __restrict__ sgn,
    const float* __restrict__ lminp, const float* __restrict__ lmaxp,
    const float* __restrict__ scale, const float* __restrict__ bias,
    float* __restrict__ out)
{
    extern __shared__ char smem[];
    const uint32_t sb = smem_u32(smem);

    // w = exp(lmin + (255-s)/254*(lmax-lmin)) = exp2(Ac + Bc*s)
    const float L2E = 1.4426950408889634f;
    float lmin = *lminp, lmax = *lmaxp;
    float d = lmax - lmin;
    float Bc = -(d * (1.0f / 254.0f)) * L2E;
    float Ac = (lmin + d * (255.0f / 254.0f)) * L2E;

    const int bid = blockIdx.x;
    if (bid < 52)
        run_gemm<64>(sb, stored, sgn, scale, bias, out, bid * 64, Ac, Bc);
    else
        run_gemm<80>(sb, stored, sgn, scale, bias, out, 3328 + (bid - 52) * 80, Ac, Bc);
}

// ---------------- launch ----------------
extern "C" void kernel_launch(void* const* d_in, const int* in_sizes, int n_in,
                              void* d_out, int out_size) {
    const float* x      = (const float*)d_in[0];
    const int*   stored = (const int*)d_in[1];
    const int*   sgn    = (const int*)d_in[2];
    const float* lmin   = (const float*)d_in[3];
    const float* lmax   = (const float*)d_in[4];
    const float* scale  = (const float*)d_in[5];
    const float* bias   = (const float*)d_in[6];
    float* out = (float*)d_out;

    cudaFuncSetAttribute(qins_gemm_kernel,
                         cudaFuncAttributeMaxDynamicSharedMemorySize, SMEM_TOTAL);

    // Pass 1: x fp32 -> fp16 scratch
    convert_x_kernel<<<(BATCH * INDIM) / (256 * 4), 256>>>(x);

    // Pass 2: one exact wave — 52 CTAs x 64ch + 96 CTAs x 80ch = 11008
    qins_gemm_kernel<<<148, NTHREADS, SMEM_TOTAL>>>(
        stored, sgn, lmin, lmax, scale, bias, out);
}